// round 5
// baseline (speedup 1.0000x reference)
#include <cuda_runtime.h>
#include <cuda_bf16.h>
#include <cstdint>
#include <cstddef>

// ---------------------------------------------------------------------------
// LSTM_87351044866551  (Round 5)
//   P: transpose+split Wi -> g_wb_hi/lo bf16 [N=512][K=2048]
//   S: split x -> g_xb_hi/lo bf16 [M=32768][K=2048]  (streaming)
//   G: xg = x@Wi via pure cp.async/ldmatrix/mma pipeline, 3-term bf16 split
//   L: LSTM recurrence, shfl gate-combine, 1 sync/step, double-buffered h
// ---------------------------------------------------------------------------

#define M_DIM 32768
#define N_DIM 512
#define K_DIM 2048

__device__ float g_xg[(size_t)M_DIM * N_DIM];                          // 64 MB
__device__ __align__(256) __nv_bfloat16 g_wb_hi[(size_t)N_DIM * K_DIM];
__device__ __align__(256) __nv_bfloat16 g_wb_lo[(size_t)N_DIM * K_DIM];
__device__ __align__(256) __nv_bfloat16 g_xb_hi[(size_t)M_DIM * K_DIM]; // 134MB
__device__ __align__(256) __nv_bfloat16 g_xb_lo[(size_t)M_DIM * K_DIM];

// ===========================================================================
// helpers (base ISA only — tcgen05 not assemblable on this harness)
// ===========================================================================
__device__ __forceinline__ uint32_t smem_u32(const void* p) {
    uint32_t a;
    asm("{ .reg .u64 t; cvta.to.shared.u64 t, %1; cvt.u32.u64 %0, t; }"
        : "=r"(a) : "l"(p));
    return a;
}
__device__ __forceinline__ void ldsm_x4(uint32_t& r0, uint32_t& r1,
                                        uint32_t& r2, uint32_t& r3,
                                        uint32_t addr) {
    asm volatile("ldmatrix.sync.aligned.m8n8.x4.shared.b16 {%0,%1,%2,%3},[%4];"
                 : "=r"(r0), "=r"(r1), "=r"(r2), "=r"(r3) : "r"(addr));
}
__device__ __forceinline__ void mma_bf16(float* d, const uint32_t* a,
                                         uint32_t b0, uint32_t b1) {
    asm volatile(
        "mma.sync.aligned.m16n8k16.row.col.f32.bf16.bf16.f32 "
        "{%0,%1,%2,%3},{%4,%5,%6,%7},{%8,%9},{%0,%1,%2,%3};"
        : "+f"(d[0]), "+f"(d[1]), "+f"(d[2]), "+f"(d[3])
        : "r"(a[0]), "r"(a[1]), "r"(a[2]), "r"(a[3]), "r"(b0), "r"(b1));
}
#define CPASYNC16(dst, src) \
    asm volatile("cp.async.cg.shared.global [%0],[%1],16;" :: "r"(dst), "l"(src))
#define CPCOMMIT() asm volatile("cp.async.commit_group;" ::: "memory")
#define CPWAIT1()  asm volatile("cp.async.wait_group 1;" ::: "memory")

__device__ __forceinline__ uint32_t pack_hi2(float a, float b) {
    __nv_bfloat162 h;
    h.x = __float2bfloat16_rn(a);
    h.y = __float2bfloat16_rn(b);
    return *(uint32_t*)&h;
}
__device__ __forceinline__ uint32_t pack_lo2(float a, float b) {
    __nv_bfloat162 h;
    h.x = __float2bfloat16_rn(a - __bfloat162float(__float2bfloat16_rn(a)));
    h.y = __float2bfloat16_rn(b - __bfloat162float(__float2bfloat16_rn(b)));
    return *(uint32_t*)&h;
}

// ===========================================================================
// Kernel P: Wb_hi/lo[n][k] = split(Wi[k][n])
// ===========================================================================
__global__ __launch_bounds__(1024) void prep_w(const float* __restrict__ Wi) {
    __shared__ float t[32][33];
    const int k = blockIdx.x * 32 + threadIdx.y;
    const int n = blockIdx.y * 32 + threadIdx.x;
    t[threadIdx.y][threadIdx.x] = Wi[(size_t)k * N_DIM + n];
    __syncthreads();
    const int n2 = blockIdx.y * 32 + threadIdx.y;
    const int k2 = blockIdx.x * 32 + threadIdx.x;
    const float v = t[threadIdx.x][threadIdx.y];
    const __nv_bfloat16 h = __float2bfloat16_rn(v);
    const __nv_bfloat16 l = __float2bfloat16_rn(v - __bfloat162float(h));
    g_wb_hi[(size_t)n2 * K_DIM + k2] = h;
    g_wb_lo[(size_t)n2 * K_DIM + k2] = l;
}

// ===========================================================================
// Kernel S: split x -> bf16 hi/lo (8 floats per thread, streaming)
// ===========================================================================
__global__ __launch_bounds__(256) void split_x(const float* __restrict__ x) {
    const size_t base = ((size_t)blockIdx.x * 256 + threadIdx.x) * 8;
    const float4 v0 = *(const float4*)(x + base);
    const float4 v1 = *(const float4*)(x + base + 4);
    uint4 hi, lo;
    hi.x = pack_hi2(v0.x, v0.y); hi.y = pack_hi2(v0.z, v0.w);
    hi.z = pack_hi2(v1.x, v1.y); hi.w = pack_hi2(v1.z, v1.w);
    lo.x = pack_lo2(v0.x, v0.y); lo.y = pack_lo2(v0.z, v0.w);
    lo.z = pack_lo2(v1.x, v1.y); lo.w = pack_lo2(v1.z, v1.w);
    *(uint4*)(g_xb_hi + base) = hi;
    *(uint4*)(g_xb_lo + base) = lo;
}

// ===========================================================================
// Kernel G: HMMA GEMM, CTA 128x256, warp 64x64, K-chunk 32, 3-stage cp.async
// Stage layout (bytes): Ahi@0 (128x40u), Alo@10240, Bhi@20480 (256x40u),
//                       Blo@40960; stage = 61440B, 3 stages = 184320B.
// ===========================================================================
#define SROWB 80                 // row stride bytes (40 bf16)
#define A_LO_OFF 10240
#define B_HI_OFF 20480
#define B_LO_OFF 40960
#define STAGE_BYTES 61440
#define GEMM_SMEM (3 * STAGE_BYTES)
#define NCHUNK 64

__global__ __launch_bounds__(256, 1) void gemm_hmma() {
    extern __shared__ __nv_bfloat16 smb[];
    const uint32_t sbase = smem_u32(smb);
    const int tid  = threadIdx.x;
    const int lane = tid & 31;
    const int w    = tid >> 5;
    const int wm   = w & 1;
    const int wn   = w >> 1;
    const int m0   = blockIdx.y * 128;
    const int n0   = blockIdx.x * 256;

    float acc[4][8][4];
#pragma unroll
    for (int a = 0; a < 4; a++)
#pragma unroll
        for (int b = 0; b < 8; b++)
#pragma unroll
            for (int c = 0; c < 4; c++) acc[a][b][c] = 0.f;

    const __nv_bfloat16* aH = g_xb_hi + (size_t)m0 * K_DIM;
    const __nv_bfloat16* aL = g_xb_lo + (size_t)m0 * K_DIM;
    const __nv_bfloat16* bH = g_wb_hi + (size_t)n0 * K_DIM;
    const __nv_bfloat16* bL = g_wb_lo + (size_t)n0 * K_DIM;

    const int pr  = tid >> 2;      // 0..63  (row base for A & B)
    const int ku  = tid & 3;       // 16B unit within 32-k chunk
    const uint32_t dstu = pr * SROWB + ku * 16;
    const size_t   srcu = (size_t)pr * K_DIM + ku * 8;

#define ISSUE(kt, s)                                                          \
    do {                                                                      \
        const uint32_t st = sbase + (s)*STAGE_BYTES;                          \
        const size_t ko = (size_t)(kt) * 32;                                  \
        CPASYNC16(st + dstu, aH + srcu + ko);                                 \
        CPASYNC16(st + dstu + A_LO_OFF, aL + srcu + ko);                      \
        CPASYNC16(st + dstu + 64 * SROWB, aH + srcu + (size_t)64 * K_DIM + ko); \
        CPASYNC16(st + dstu + 64 * SROWB + A_LO_OFF,                          \
                  aL + srcu + (size_t)64 * K_DIM + ko);                       \
        _Pragma("unroll")                                                     \
        for (int j = 0; j < 4; j++) {                                         \
            const uint32_t d = st + B_HI_OFF + dstu + j * 64 * SROWB;         \
            const size_t gsrc = srcu + (size_t)j * 64 * K_DIM + ko;           \
            CPASYNC16(d, bH + gsrc);                                          \
            CPASYNC16(d + (B_LO_OFF - B_HI_OFF), bL + gsrc);                  \
        }                                                                     \
    } while (0)

    // prologue: chunks 0,1 as groups 0,1
    ISSUE(0, 0); CPCOMMIT();
    ISSUE(1, 1); CPCOMMIT();

    // ldmatrix lane addressing
    const int a_row = (lane & 7) + ((lane >> 3) & 1) * 8;
    const int a_kb  = ((lane >> 4) & 1) * 16;
    const int b_row = (lane & 7) + ((lane >> 4) & 1) * 8;
    const int b_kb  = ((lane >> 3) & 1) * 16;

    for (int kt = 0; kt < NCHUNK; kt++) {
        const int s = kt % 3;
        CPWAIT1();            // all groups except newest 1 complete -> chunk kt in
        __syncthreads();      // also: all warps done with MMA(kt-1) -> stage reuse safe
        if (kt + 2 < NCHUNK) ISSUE(kt + 2, (kt + 2) % 3);
        CPCOMMIT();           // always commit (keeps group count uniform)

        const uint32_t stg = sbase + s * STAGE_BYTES;
#pragma unroll
        for (int kk = 0; kk < 2; kk++) {
            uint32_t ah[4][4], al[4][4];
#pragma unroll
            for (int mi = 0; mi < 4; mi++) {
                const uint32_t aaddr =
                    stg + (wm * 64 + mi * 16 + a_row) * SROWB + kk * 32 + a_kb;
                ldsm_x4(ah[mi][0], ah[mi][1], ah[mi][2], ah[mi][3], aaddr);
                ldsm_x4(al[mi][0], al[mi][1], al[mi][2], al[mi][3],
                        aaddr + A_LO_OFF);
            }
#pragma unroll
            for (int np = 0; np < 4; np++) {
                const uint32_t baddr = stg + B_HI_OFF +
                    (wn * 64 + np * 16 + b_row) * SROWB + kk * 32 + b_kb;
                uint32_t bh0, bh1, bh2, bh3, bl0, bl1, bl2, bl3;
                ldsm_x4(bh0, bh1, bh2, bh3, baddr);
                ldsm_x4(bl0, bl1, bl2, bl3, baddr + (B_LO_OFF - B_HI_OFF));
#pragma unroll
                for (int mi = 0; mi < 4; mi++) {
                    mma_bf16(acc[mi][np * 2],     ah[mi], bh0, bh1);
                    mma_bf16(acc[mi][np * 2 + 1], ah[mi], bh2, bh3);
                }
#pragma unroll
                for (int mi = 0; mi < 4; mi++) {
                    mma_bf16(acc[mi][np * 2],     al[mi], bh0, bh1);
                    mma_bf16(acc[mi][np * 2 + 1], al[mi], bh2, bh3);
                }
#pragma unroll
                for (int mi = 0; mi < 4; mi++) {
                    mma_bf16(acc[mi][np * 2],     ah[mi], bl0, bl1);
                    mma_bf16(acc[mi][np * 2 + 1], ah[mi], bl2, bl3);
                }
            }
        }
    }
#undef ISSUE

    // epilogue
#pragma unroll
    for (int mi = 0; mi < 4; mi++)
#pragma unroll
        for (int ni = 0; ni < 8; ni++) {
            const int row = m0 + wm * 64 + mi * 16 + (lane >> 2);
            const int col = n0 + wn * 64 + ni * 8 + (lane & 3) * 2;
            float* p = g_xg + (size_t)row * N_DIM + col;
            float2 v0, v1;
            v0.x = acc[mi][ni][0]; v0.y = acc[mi][ni][1];
            v1.x = acc[mi][ni][2]; v1.y = acc[mi][ni][3];
            *(float2*)p = v0;
            *(float2*)(p + 8 * N_DIM) = v1;
        }
}

// ===========================================================================
// Kernel L: LSTM recurrence v2 — shfl gate combine, 1 sync/step
//   warp layout: lane = gate*8 + jj; warp w: bl = w>>3, w8 = w&7
//   thread columns: col_s = gate*128 + (w8*8 + jj) + s*64, s in {0,1}
//   h double-buffered: hs[2][2][128]
// ===========================================================================
__device__ __forceinline__ float ftanh(float x) {
    return 1.f - 2.f / (__expf(2.f * x) + 1.f);
}

#define US_FLOATS (512 * 108)
#define SM2_FLOATS (US_FLOATS + 512 + 64)

__global__ __launch_bounds__(512) void lstm_rec(const float* __restrict__ Uh,
                                                const float* __restrict__ bias,
                                                const float* __restrict__ Wout,
                                                const float* __restrict__ bout,
                                                float* __restrict__ out) {
    extern __shared__ float smf[];
    float* Us  = smf;                 // [512][108]
    float* hs  = smf + US_FLOATS;     // [2 buf][2 batch][128]
    float* red = hs + 512;            // head scratch

    const int tid = threadIdx.x;
    const int w    = tid >> 5;
    const int lane = tid & 31;
    const int bl   = w >> 3;
    const int w8   = w & 7;
    const int gate = lane >> 3;
    const int jj   = lane & 7;
    const int j0   = w8 * 8 + jj;
    const int j1   = j0 + 64;
    const int col0 = gate * 128 + j0;
    const int col1 = gate * 128 + j1;
    const int b0   = blockIdx.x * 2;

    // cooperative Uh load: thread g fills column g rows 0..103 (coalesced)
    for (int k = 0; k < 104; k++) Us[tid * 108 + k] = Uh[k * 512 + tid];
    float wr0[24], wr1[24];
#pragma unroll
    for (int r = 0; r < 24; r++) {
        wr0[r] = Uh[(104 + r) * 512 + col0];
        wr1[r] = Uh[(104 + r) * 512 + col1];
    }
    const float bg0 = bias[col0];
    const float bg1 = bias[col1];

    if (tid < 256) { hs[tid] = 0.f; hs[256 + tid] = 0.f; }
    float c0 = 0.f, c1 = 0.f;
    __syncthreads();

    const float* xp = g_xg + ((size_t)(b0 + bl) * 128) * 512;
    float xa = xp[col0];
    float xb = xp[col1];
    const bool isg = (gate == 2);

    for (int t = 0; t < 128; t++) {
        float z0 = xa + bg0;
        float z1 = xb + bg1;
        if (t + 1 < 128) {
            xa = xp[(t + 1) * 512 + col0];
            xb = xp[(t + 1) * 512 + col1];
        }
        const int rb = t & 1;
        const float* hb = hs + rb * 256 + bl * 128;
        const float4* u0 = (const float4*)(Us + col0 * 108);
        const float4* u1 = (const float4*)(Us + col1 * 108);
        const float4* hv = (const float4*)hb;
#pragma unroll
        for (int q = 0; q < 26; q++) {
            const float4 h4 = hv[q];
            const float4 a4 = u0[q];
            const float4 b4 = u1[q];
            z0 += a4.x * h4.x; z0 += a4.y * h4.y;
            z0 += a4.z * h4.z; z0 += a4.w * h4.w;
            z1 += b4.x * h4.x; z1 += b4.y * h4.y;
            z1 += b4.z * h4.z; z1 += b4.w * h4.w;
        }
#pragma unroll
        for (int r = 0; r < 24; r++) {
            const float hk = hb[104 + r];
            z0 += wr0[r] * hk;
            z1 += wr1[r] * hk;
        }
        // branchless activation (gate 2 -> tanh, else sigmoid)
        const float e0 = __expf(isg ? 2.f * z0 : -z0);
        const float a0 = isg ? (1.f - 2.f / (e0 + 1.f)) : (1.f / (1.f + e0));
        const float e1 = __expf(isg ? 2.f * z1 : -z1);
        const float a1 = isg ? (1.f - 2.f / (e1 + 1.f)) : (1.f / (1.f + e1));

        // gather i,f,g,o for columns j0/j1 via warp shuffle
        const float i0 = __shfl_sync(0xffffffffu, a0, jj);
        const float f0 = __shfl_sync(0xffffffffu, a0, 8 + jj);
        const float g0 = __shfl_sync(0xffffffffu, a0, 16 + jj);
        const float o0 = __shfl_sync(0xffffffffu, a0, 24 + jj);
        const float i1 = __shfl_sync(0xffffffffu, a1, jj);
        const float f1 = __shfl_sync(0xffffffffu, a1, 8 + jj);
        const float g1 = __shfl_sync(0xffffffffu, a1, 16 + jj);
        const float o1 = __shfl_sync(0xffffffffu, a1, 24 + jj);

        c0 = f0 * c0 + i0 * g0;
        c1 = f1 * c1 + i1 * g1;

        float* hw = hs + (rb ^ 1) * 256 + bl * 128;
        if (gate == 0) {
            hw[j0] = o0 * ftanh(c0);
            hw[j1] = o1 * ftanh(c1);
        }
        __syncthreads();
    }

    // output head: final h is in buffer 0 (t=127 wrote rb^1 = 0)
    if (tid < 256) {
        const int bb = tid >> 7;
        const int hj = tid & 127;
        const float h = hs[bb * 128 + hj];
        float p0 = h * Wout[hj * 2 + 0];
        float p1 = h * Wout[hj * 2 + 1];
#pragma unroll
        for (int off = 16; off > 0; off >>= 1) {
            p0 += __shfl_down_sync(0xffffffffu, p0, off);
            p1 += __shfl_down_sync(0xffffffffu, p1, off);
        }
        if ((tid & 31) == 0) {
            red[(tid >> 5) * 2 + 0] = p0;
            red[(tid >> 5) * 2 + 1] = p1;
        }
    }
    __syncthreads();
    if (tid < 2) {
        float s0 = bout[0], s1 = bout[1];
#pragma unroll
        for (int q = 0; q < 4; q++) {
            s0 += red[(tid * 4 + q) * 2 + 0];
            s1 += red[(tid * 4 + q) * 2 + 1];
        }
        out[(b0 + tid) * 2 + 0] = s0;
        out[(b0 + tid) * 2 + 1] = s1;
    }
}

// ===========================================================================
extern "C" void kernel_launch(void* const* d_in, const int* in_sizes, int n_in,
                              void* d_out, int out_size) {
    const float* x    = (const float*)d_in[0];
    const float* Wi   = (const float*)d_in[1];
    const float* Uh   = (const float*)d_in[2];
    const float* b    = (const float*)d_in[3];
    const float* Wout = (const float*)d_in[4];
    const float* bout = (const float*)d_in[5];
    float* out = (float*)d_out;

    dim3 gp(K_DIM / 32, N_DIM / 32);
    prep_w<<<gp, dim3(32, 32)>>>(Wi);

    split_x<<<(int)((size_t)M_DIM * K_DIM / (256 * 8)), 256>>>(x);

    cudaFuncSetAttribute(gemm_hmma, cudaFuncAttributeMaxDynamicSharedMemorySize,
                         GEMM_SMEM);
    dim3 gg(N_DIM / 256, M_DIM / 128);          // (2, 256)
    gemm_hmma<<<gg, 256, GEMM_SMEM>>>();

    const size_t smem2 = SM2_FLOATS * sizeof(float);
    cudaFuncSetAttribute(lstm_rec, cudaFuncAttributeMaxDynamicSharedMemorySize,
                         (int)smem2);
    lstm_rec<<<128, 512, smem2>>>(Uh, b, Wout, bout, out);
}

// round 6
// speedup vs baseline: 1.2521x; 1.2521x over previous
#include <cuda_runtime.h>
#include <cuda_bf16.h>
#include <cstdint>
#include <cstddef>

// ---------------------------------------------------------------------------
// LSTM_87351044866551  (Round 6)
//   P: transpose+split Wi -> g_wb_hi/lo bf16 [N=512][K=2048]
//   G: xg = x@Wi, HMMA 3-term bf16 split; 512 thr, warp 32x64 (4 warps/SMSP)
//   L: LSTM recurrence v3: v1 structure + 64-reg Uh rows + float4 h broadcasts
// ---------------------------------------------------------------------------

#define M_DIM 32768
#define N_DIM 512
#define K_DIM 2048

__device__ float g_xg[(size_t)M_DIM * N_DIM];            // 64 MB scratch
__device__ __align__(256) __nv_bfloat16 g_wb_hi[(size_t)N_DIM * K_DIM];
__device__ __align__(256) __nv_bfloat16 g_wb_lo[(size_t)N_DIM * K_DIM];

// ===========================================================================
// helpers (base ISA only — tcgen05 not assemblable on this harness)
// ===========================================================================
__device__ __forceinline__ uint32_t smem_u32(const void* p) {
    uint32_t a;
    asm("{ .reg .u64 t; cvta.to.shared.u64 t, %1; cvt.u32.u64 %0, t; }"
        : "=r"(a) : "l"(p));
    return a;
}
__device__ __forceinline__ void ldsm_x4(uint32_t& r0, uint32_t& r1,
                                        uint32_t& r2, uint32_t& r3,
                                        uint32_t addr) {
    asm volatile("ldmatrix.sync.aligned.m8n8.x4.shared.b16 {%0,%1,%2,%3},[%4];"
                 : "=r"(r0), "=r"(r1), "=r"(r2), "=r"(r3) : "r"(addr));
}
__device__ __forceinline__ void mma_bf16(float* d, const uint32_t* a,
                                         uint32_t b0, uint32_t b1) {
    asm volatile(
        "mma.sync.aligned.m16n8k16.row.col.f32.bf16.bf16.f32 "
        "{%0,%1,%2,%3},{%4,%5,%6,%7},{%8,%9},{%0,%1,%2,%3};"
        : "+f"(d[0]), "+f"(d[1]), "+f"(d[2]), "+f"(d[3])
        : "r"(a[0]), "r"(a[1]), "r"(a[2]), "r"(a[3]), "r"(b0), "r"(b1));
}
#define CPASYNC16(dst, src) \
    asm volatile("cp.async.cg.shared.global [%0],[%1],16;" :: "r"(dst), "l"(src))
#define CPCOMMIT() asm volatile("cp.async.commit_group;" ::: "memory")
#define CPWAIT0()  asm volatile("cp.async.wait_group 0;" ::: "memory")

// ===========================================================================
// Kernel P: Wb_hi/lo[n][k] = split(Wi[k][n])
// ===========================================================================
__global__ __launch_bounds__(1024) void prep_w(const float* __restrict__ Wi) {
    __shared__ float t[32][33];
    const int k = blockIdx.x * 32 + threadIdx.y;
    const int n = blockIdx.y * 32 + threadIdx.x;
    t[threadIdx.y][threadIdx.x] = Wi[(size_t)k * N_DIM + n];
    __syncthreads();
    const int n2 = blockIdx.y * 32 + threadIdx.y;
    const int k2 = blockIdx.x * 32 + threadIdx.x;
    const float v = t[threadIdx.x][threadIdx.y];
    const __nv_bfloat16 h = __float2bfloat16_rn(v);
    const __nv_bfloat16 l = __float2bfloat16_rn(v - __bfloat162float(h));
    g_wb_hi[(size_t)n2 * K_DIM + k2] = h;
    g_wb_lo[(size_t)n2 * K_DIM + k2] = l;
}

// ===========================================================================
// Kernel G: HMMA GEMM, CTA 128x256, 512 thr, warp 32x64, K-chunk 32, 2-stage
// Stage (bytes): Ahi@0 (128x80), Alo@10240, Bhi@20480 (256x80), Blo@40960
// ===========================================================================
#define SROWB 80
#define A_LO_OFF 10240
#define B_HI_OFF 20480
#define B_LO_OFF 40960
#define STAGE_BYTES 61440
#define GEMM_SMEM (2 * STAGE_BYTES)
#define NCHUNK 64

__global__ __launch_bounds__(512, 1) void gemm_hmma(const float* __restrict__ x) {
    extern __shared__ __nv_bfloat16 smb[];
    const uint32_t sbase = smem_u32(smb);
    const int tid  = threadIdx.x;
    const int lane = tid & 31;
    const int w    = tid >> 5;
    const int wm   = w & 3;          // 4 M-warps of 32 rows
    const int wn   = w >> 2;         // 4 N-warps of 64 cols
    const int m0   = blockIdx.y * 128;
    const int n0   = blockIdx.x * 256;

    float acc[2][8][4];
#pragma unroll
    for (int a = 0; a < 2; a++)
#pragma unroll
        for (int b = 0; b < 8; b++)
#pragma unroll
            for (int c = 0; c < 4; c++) acc[a][b][c] = 0.f;

    const float* xA = x + (size_t)m0 * K_DIM;
    const __nv_bfloat16* bH = g_wb_hi + (size_t)n0 * K_DIM;
    const __nv_bfloat16* bL = g_wb_lo + (size_t)n0 * K_DIM;

    float4 av[2];

    // A: 1024 float4/chunk -> 2/thread; idx -> r=idx>>3, f4=idx&7
#define LDG_A(kt)                                                              \
    do {                                                                       \
        _Pragma("unroll")                                                      \
        for (int i = 0; i < 2; i++) {                                          \
            const int idx = tid + i * 512;                                     \
            const int r = idx >> 3, f4 = idx & 7;                              \
            av[i] = *(const float4*)(xA + (size_t)r * K_DIM + (kt) * 32 + f4 * 4); \
        }                                                                      \
    } while (0)

#define STS_A(s)                                                               \
    do {                                                                       \
        _Pragma("unroll")                                                      \
        for (int i = 0; i < 2; i++) {                                          \
            const int idx = tid + i * 512;                                     \
            const int r = idx >> 3, f4 = idx & 7;                              \
            const float4 v = av[i];                                            \
            __nv_bfloat16 hx = __float2bfloat16_rn(v.x);                       \
            __nv_bfloat16 hy = __float2bfloat16_rn(v.y);                       \
            __nv_bfloat16 hz = __float2bfloat16_rn(v.z);                       \
            __nv_bfloat16 hw = __float2bfloat16_rn(v.w);                       \
            __nv_bfloat16 lx = __float2bfloat16_rn(v.x - __bfloat162float(hx)); \
            __nv_bfloat16 ly = __float2bfloat16_rn(v.y - __bfloat162float(hy)); \
            __nv_bfloat16 lz = __float2bfloat16_rn(v.z - __bfloat162float(hz)); \
            __nv_bfloat16 lw = __float2bfloat16_rn(v.w - __bfloat162float(hw)); \
            __nv_bfloat162 h01, h23, l01, l23;                                 \
            h01.x = hx; h01.y = hy; h23.x = hz; h23.y = hw;                    \
            l01.x = lx; l01.y = ly; l23.x = lz; l23.y = lw;                    \
            uint2 hp, lp;                                                      \
            hp.x = *(uint32_t*)&h01; hp.y = *(uint32_t*)&h23;                  \
            lp.x = *(uint32_t*)&l01; lp.y = *(uint32_t*)&l23;                  \
            char* base = (char*)smb + (s) * STAGE_BYTES + r * SROWB + f4 * 8;  \
            *(uint2*)base              = hp;                                   \
            *(uint2*)(base + A_LO_OFF) = lp;                                   \
        }                                                                      \
    } while (0)

    // B: 1024 16B units per array per chunk -> 2 idx/thread, hi+lo each
#define CPA_B(kt, s)                                                           \
    do {                                                                       \
        _Pragma("unroll")                                                      \
        for (int i = 0; i < 2; i++) {                                          \
            const int idx = tid + i * 512;                                     \
            const int n = idx >> 2, ku = idx & 3;                              \
            const size_t gsrc = (size_t)n * K_DIM + (kt) * 32 + ku * 8;        \
            const uint32_t d =                                                 \
                sbase + (s) * STAGE_BYTES + B_HI_OFF + n * SROWB + ku * 16;    \
            CPASYNC16(d, bH + gsrc);                                           \
            CPASYNC16(d + (B_LO_OFF - B_HI_OFF), bL + gsrc);                   \
        }                                                                      \
    } while (0)

    // prologue
    LDG_A(0);
    CPA_B(0, 0);
    CPCOMMIT();
    STS_A(0);
    CPWAIT0();
    __syncthreads();

    const int a_row = (lane & 7) + ((lane >> 3) & 1) * 8;
    const int a_kb  = ((lane >> 4) & 1) * 16;
    const int b_row = (lane & 7) + ((lane >> 4) & 1) * 8;
    const int b_kb  = ((lane >> 3) & 1) * 16;

    for (int kt = 0; kt < NCHUNK; kt++) {
        const int s = kt & 1;
        if (kt + 1 < NCHUNK) {
            LDG_A(kt + 1);
            CPA_B(kt + 1, s ^ 1);
            CPCOMMIT();
        }

        const uint32_t stg = sbase + s * STAGE_BYTES;
#pragma unroll
        for (int kk = 0; kk < 2; kk++) {
            uint32_t ah[2][4], al[2][4];
#pragma unroll
            for (int mi = 0; mi < 2; mi++) {
                const uint32_t aaddr =
                    stg + (wm * 32 + mi * 16 + a_row) * SROWB + kk * 32 + a_kb;
                ldsm_x4(ah[mi][0], ah[mi][1], ah[mi][2], ah[mi][3], aaddr);
                ldsm_x4(al[mi][0], al[mi][1], al[mi][2], al[mi][3],
                        aaddr + A_LO_OFF);
            }
#pragma unroll
            for (int np = 0; np < 4; np++) {
                const uint32_t baddr = stg + B_HI_OFF +
                    (wn * 64 + np * 16 + b_row) * SROWB + kk * 32 + b_kb;
                uint32_t bh0, bh1, bh2, bh3, bl0, bl1, bl2, bl3;
                ldsm_x4(bh0, bh1, bh2, bh3, baddr);
                ldsm_x4(bl0, bl1, bl2, bl3, baddr + (B_LO_OFF - B_HI_OFF));
#pragma unroll
                for (int mi = 0; mi < 2; mi++) {
                    mma_bf16(acc[mi][np * 2],     ah[mi], bh0, bh1);
                    mma_bf16(acc[mi][np * 2 + 1], ah[mi], bh2, bh3);
                }
#pragma unroll
                for (int mi = 0; mi < 2; mi++) {
                    mma_bf16(acc[mi][np * 2],     al[mi], bh0, bh1);
                    mma_bf16(acc[mi][np * 2 + 1], al[mi], bh2, bh3);
                }
#pragma unroll
                for (int mi = 0; mi < 2; mi++) {
                    mma_bf16(acc[mi][np * 2],     ah[mi], bl0, bl1);
                    mma_bf16(acc[mi][np * 2 + 1], ah[mi], bl2, bl3);
                }
            }
        }

        if (kt + 1 < NCHUNK) {
            STS_A(s ^ 1);
            CPWAIT0();
        }
        __syncthreads();
    }
#undef LDG_A
#undef STS_A
#undef CPA_B

    // epilogue
#pragma unroll
    for (int mi = 0; mi < 2; mi++)
#pragma unroll
        for (int ni = 0; ni < 8; ni++) {
            const int row = m0 + wm * 32 + mi * 16 + (lane >> 2);
            const int col = n0 + wn * 64 + ni * 8 + (lane & 3) * 2;
            float* p = g_xg + (size_t)row * N_DIM + col;
            float2 v0, v1;
            v0.x = acc[mi][ni][0]; v0.y = acc[mi][ni][1];
            v1.x = acc[mi][ni][2]; v1.y = acc[mi][ni][3];
            *(float2*)p = v0;
            *(float2*)(p + 8 * N_DIM) = v1;
        }
}

// ===========================================================================
// Kernel L: LSTM recurrence v3 — v1 structure, Uh rows 64..127 in registers,
// all h reads vectorized float4 broadcasts.
// ===========================================================================
__device__ __forceinline__ float fsig(float x) { return 1.f / (1.f + __expf(-x)); }
__device__ __forceinline__ float ftanh(float x) { return 1.f - 2.f / (__expf(2.f * x) + 1.f); }

#define USTRIDE 68
#define US_FLOATS (512 * USTRIDE)
#define SM2_FLOATS (US_FLOATS + 256 + 1024)

__global__ __launch_bounds__(512) void lstm_rec(const float* __restrict__ Uh,
                                                const float* __restrict__ bias,
                                                const float* __restrict__ Wout,
                                                const float* __restrict__ bout,
                                                float* __restrict__ out) {
    extern __shared__ float smf[];
    float* Us = smf;                 // [512][68], rows 0..63 of Uh per column
    float* hs = smf + US_FLOATS;     // [2][128]
    float* zs = hs + 256;            // [2][512]

    const int tid = threadIdx.x;
    const int g   = tid;
    const int b0  = blockIdx.x * 2;

    for (int k = 0; k < 64; k++) Us[g * USTRIDE + k] = Uh[k * 512 + g];
    float wreg[64];
#pragma unroll
    for (int r = 0; r < 64; r++) wreg[r] = Uh[(64 + r) * 512 + g];
    const float bg   = bias[g];
    const int  gate  = g >> 7;

    if (tid < 256) hs[tid] = 0.f;
    float c = 0.f;
    __syncthreads();

    const float* xp0 = g_xg + ((size_t)b0 * 128) * 512 + g;
    const float* xp1 = g_xg + ((size_t)(b0 + 1) * 128) * 512 + g;
    float x0 = xp0[0];
    float x1 = xp1[0];

    for (int t = 0; t < 128; t++) {
        float z0 = x0 + bg;
        float z1 = x1 + bg;
        if (t + 1 < 128) {
            x0 = xp0[(t + 1) * 512];
            x1 = xp1[(t + 1) * 512];
        }

        const float4* uv = (const float4*)(Us + g * USTRIDE);
        const float4* h0 = (const float4*)hs;
        const float4* h1 = (const float4*)(hs + 128);
        // SMEM part: k = 0..63
#pragma unroll
        for (int q = 0; q < 16; q++) {
            const float4 u  = uv[q];
            const float4 ha = h0[q];
            const float4 hb = h1[q];
            z0 += u.x * ha.x; z0 += u.y * ha.y; z0 += u.z * ha.z; z0 += u.w * ha.w;
            z1 += u.x * hb.x; z1 += u.y * hb.y; z1 += u.z * hb.z; z1 += u.w * hb.w;
        }
        // register part: k = 64..127, h via float4 broadcast
#pragma unroll
        for (int q = 0; q < 16; q++) {
            const float4 ha = h0[16 + q];
            const float4 hb = h1[16 + q];
            z0 += wreg[q * 4 + 0] * ha.x; z0 += wreg[q * 4 + 1] * ha.y;
            z0 += wreg[q * 4 + 2] * ha.z; z0 += wreg[q * 4 + 3] * ha.w;
            z1 += wreg[q * 4 + 0] * hb.x; z1 += wreg[q * 4 + 1] * hb.y;
            z1 += wreg[q * 4 + 2] * hb.z; z1 += wreg[q * 4 + 3] * hb.w;
        }

        float a0, a1;
        if (gate == 2) { a0 = ftanh(z0); a1 = ftanh(z1); }
        else           { a0 = fsig(z0);  a1 = fsig(z1);  }
        zs[g]       = a0;
        zs[512 + g] = a1;
        __syncthreads();

        if (tid < 256) {
            const int bl = tid >> 7;
            const int jj = tid & 127;
            const float* zb = zs + bl * 512;
            const float ig = zb[jj];
            const float fg = zb[128 + jj];
            const float gg = zb[256 + jj];
            const float og = zb[384 + jj];
            c = fg * c + ig * gg;
            hs[bl * 128 + jj] = og * ftanh(c);
        }
        __syncthreads();
    }

    if (tid < 256) {
        const int bl = tid >> 7;
        const int jj = tid & 127;
        const float h = hs[bl * 128 + jj];
        float p0 = h * Wout[jj * 2 + 0];
        float p1 = h * Wout[jj * 2 + 1];
#pragma unroll
        for (int off = 16; off > 0; off >>= 1) {
            p0 += __shfl_down_sync(0xffffffffu, p0, off);
            p1 += __shfl_down_sync(0xffffffffu, p1, off);
        }
        if ((tid & 31) == 0) {
            const int w = tid >> 5;
            zs[w * 2 + 0] = p0;
            zs[w * 2 + 1] = p1;
        }
    }
    __syncthreads();
    if (tid < 2) {
        float s0 = bout[0], s1 = bout[1];
#pragma unroll
        for (int w = 0; w < 4; w++) {
            s0 += zs[(tid * 4 + w) * 2 + 0];
            s1 += zs[(tid * 4 + w) * 2 + 1];
        }
        out[(b0 + tid) * 2 + 0] = s0;
        out[(b0 + tid) * 2 + 1] = s1;
    }
}

// ===========================================================================
extern "C" void kernel_launch(void* const* d_in, const int* in_sizes, int n_in,
                              void* d_out, int out_size) {
    const float* x    = (const float*)d_in[0];
    const float* Wi   = (const float*)d_in[1];
    const float* Uh   = (const float*)d_in[2];
    const float* b    = (const float*)d_in[3];
    const float* Wout = (const float*)d_in[4];
    const float* bout = (const float*)d_in[5];
    float* out = (float*)d_out;

    dim3 gp(K_DIM / 32, N_DIM / 32);
    prep_w<<<gp, dim3(32, 32)>>>(Wi);

    cudaFuncSetAttribute(gemm_hmma, cudaFuncAttributeMaxDynamicSharedMemorySize,
                         GEMM_SMEM);
    dim3 gg(N_DIM / 256, M_DIM / 128);          // (2, 256)
    gemm_hmma<<<gg, 512, GEMM_SMEM>>>(x);

    const size_t smem2 = SM2_FLOATS * sizeof(float);
    cudaFuncSetAttribute(lstm_rec, cudaFuncAttributeMaxDynamicSharedMemorySize,
                         (int)smem2);
    lstm_rec<<<128, 512, smem2>>>(Uh, b, Wout, bout, out);
}